// round 5
// baseline (speedup 1.0000x reference)
#include <cuda_runtime.h>
#include <cuda_fp16.h>
#include <cstdint>

#define MM 16
#define KK 8192
#define NN 8192
#define KCH 8            // split-K chunks
#define K8_PER_CH 128    // packed rows per chunk (1024 rows total / 8)

// fp32 partials: [KCH][M][N]
__device__ float g_partial[KCH * MM * NN];

// Literal transcription of the reference:
//   q   = (qweight[k8, n] >> (4*j)) & 0xF          (k = k8*8 + j, LSB-first)
//   w   = fp16(q - 8) * fp16(scales[k/128, n])     (fp16 multiply, like jax)
//   acc += fp32(fp16(x[m, k])) * fp32(w)           (fp32 accumulation)
// No shared memory, no bit tricks, no inline PTX, no fused index algebra.
__global__ __launch_bounds__(128)
void ref_gemm_literal(const float* __restrict__ x,
                      const int* __restrict__ qw,
                      const float* __restrict__ sc) {
    const int n  = blockIdx.x * 128 + threadIdx.x;   // 0..8191
    const int m  = blockIdx.y;                       // 0..15
    const int kc = blockIdx.z;                       // 0..7

    float acc = 0.0f;

    for (int k8 = kc * K8_PER_CH; k8 < (kc + 1) * K8_PER_CH; ++k8) {
        const unsigned word = (unsigned)qw[(size_t)k8 * NN + n];
#pragma unroll
        for (int j = 0; j < 8; ++j) {
            const int k = k8 * 8 + j;
            const int q = (int)((word >> (4 * j)) & 0xFu);

            // fp16 dequant exactly as the reference does it
            const __half hq = __int2half_rn(q - 8);                       // exact
            const __half hs = __float2half_rn(sc[(size_t)(k >> 7) * NN + n]); // exact recover
            const __half hw = __hmul(hq, hs);                             // single fp16 rounding

            const float xa = __half2float(__float2half_rn(x[(size_t)m * KK + k]));
            acc += xa * __half2float(hw);
        }
    }

    g_partial[((size_t)kc * MM + m) * NN + n] = acc;
}

__global__ __launch_bounds__(256)
void reduce_bias_kernel(const float* __restrict__ bias, float* __restrict__ out) {
    const int i = blockIdx.x * 256 + threadIdx.x;
    if (i >= MM * NN) return;
    float s = g_partial[i];
#pragma unroll
    for (int c = 1; c < KCH; ++c) s += g_partial[(size_t)c * MM * NN + i];

    const int nn = i & (NN - 1);
    // Reference fp16 epilogue: fp16(dot) + fp16(bias), evaluated in fp16.
    const __half h  = __float2half_rn(s);
    const __half hb = __float2half_rn(bias[nn]);
    out[i] = __half2float(__hadd(h, hb));
}

extern "C" void kernel_launch(void* const* d_in, const int* in_sizes, int n_in,
                              void* d_out, int out_size) {
    // Identify inputs by element count (all distinct).
    const float* x    = nullptr;   // 16*8192     = 131072
    const int*   qw   = nullptr;   // 1024*8192   = 8388608
    const float* sc   = nullptr;   // 64*8192     = 524288
    const float* bias = nullptr;   // 8192
    for (int i = 0; i < n_in; ++i) {
        switch (in_sizes[i]) {
            case 131072:  x    = (const float*)d_in[i]; break;
            case 8388608: qw   = (const int*)d_in[i];   break;
            case 524288:  sc   = (const float*)d_in[i]; break;
            case 8192:    bias = (const float*)d_in[i]; break;
            default: break;
        }
    }
    float* out = (float*)d_out;

    dim3 grid(NN / 128, MM, KCH);      // (64, 16, 8)
    ref_gemm_literal<<<grid, 128>>>(x, qw, sc);

    reduce_bias_kernel<<<(MM * NN) / 256, 256>>>(bias, out);
}

// round 6
// speedup vs baseline: 15.0330x; 15.0330x over previous
#include <cuda_runtime.h>
#include <cuda_fp16.h>
#include <cstdint>

#define MM 16
#define KK 8192
#define NN 8192
#define KCH 8            // split-K chunks
#define KC 1024          // k per chunk (8 groups of 128)
#define BLOCK_N 128      // 8 warps * n16
#define S_H 1032         // smem x row stride in halves (1024+8 -> conflict-free quads)

// fp32 partials: [KCH][M][N]
__device__ float g_partial[KCH * MM * NN];

__device__ __forceinline__ void mma16816(float c[4],
                                         unsigned a0, unsigned a1, unsigned a2, unsigned a3,
                                         unsigned b0, unsigned b1) {
    asm volatile(
        "mma.sync.aligned.m16n8k16.row.col.f32.f16.f16.f32 "
        "{%0,%1,%2,%3}, {%4,%5,%6,%7}, {%8,%9}, {%0,%1,%2,%3};\n"
        : "+f"(c[0]), "+f"(c[1]), "+f"(c[2]), "+f"(c[3])
        : "r"(a0), "r"(a1), "r"(a2), "r"(a3), "r"(b0), "r"(b1));
}

// Nibbles 2t (low), 2t+1 (high) of w -> fp16x2 ((q-8)*s, ...), bit-exact vs reference.
// CRITICAL: mask v to 8 bits so v's own bits[16:20) don't OR into the high half.
__device__ __forceinline__ unsigned dq(unsigned w, int sh, __half2 s2) {
    unsigned v = (w >> sh) & 0xFFu;                            // <-- the fix
    unsigned h = ((v | (v << 12)) & 0x000F000Fu) | 0x64006400u;
    __half2 hv = *reinterpret_cast<__half2*>(&h);
    const __half2 c1032 = __float2half2_rn(1032.0f);
    __half2 r = __hmul2(__hsub2(hv, c1032), s2);               // exact q-8, one rounding
    return *reinterpret_cast<unsigned*>(&r);
}

__global__ __launch_bounds__(256)
void q4_gemm_mma(const float* __restrict__ x,      // fp16 values stored as fp32
                 const int* __restrict__ qw,
                 const float* __restrict__ scales) {
    __shared__ __align__(16) __half xs[MM * S_H];

    const int tid = threadIdx.x;
    const int nbase_blk = blockIdx.x * BLOCK_N;
    const int kc = blockIdx.y;

    // Stage x chunk [16][1024]: fp32 -> fp16 (exact round-trip) -> smem.
    for (int i = tid; i < MM * (KC / 4); i += 256) {
        int m = i >> 8;            // 256 float4 per row
        int off = i & 255;
        float4 v = *reinterpret_cast<const float4*>(x + (size_t)m * KK + kc * KC + off * 4);
        __half2 h01 = __floats2half2_rn(v.x, v.y);
        __half2 h23 = __floats2half2_rn(v.z, v.w);
        uint2 pk;
        pk.x = *reinterpret_cast<unsigned*>(&h01);
        pk.y = *reinterpret_cast<unsigned*>(&h23);
        *reinterpret_cast<uint2*>(&xs[m * S_H + off * 4]) = pk;
    }
    __syncthreads();

    const int warp = tid >> 5;
    const int lane = tid & 31;
    const int g = lane >> 2;     // 0..7
    const int t = lane & 3;      // 0..3
    const int sh = t * 8;

    const int nbase = nbase_blk + warp * 16;
    const int n0 = nbase + g;        // tile0 column
    const int n1 = nbase + 8 + g;    // tile1 column

    float c0[4] = {0.f, 0.f, 0.f, 0.f};
    float c1[4] = {0.f, 0.f, 0.f, 0.f};

    const unsigned* xw = reinterpret_cast<const unsigned*>(xs);
    const int* qbase = qw + (size_t)(kc * (KC / 8)) * NN;

    for (int grp = 0; grp < 8; ++grp) {
        const int gidx = kc * 8 + grp;
        const __half s0 = __float2half_rn(__ldg(scales + (size_t)gidx * NN + n0));
        const __half s1 = __float2half_rn(__ldg(scales + (size_t)gidx * NN + n1));
        const __half2 s20 = __half2half2(s0);
        const __half2 s21 = __half2half2(s1);

#pragma unroll
        for (int kk = 0; kk < 8; ++kk) {
            const int kt = grp * 8 + kk;     // k16 step within chunk
            const int kwo = kt * 8;          // word offset within smem row

            // A fragments (bank = (4g+t) mod 32 across the warp -> conflict-free)
            unsigned a0 = xw[g * (S_H / 2) + kwo + t];
            unsigned a1 = xw[(g + 8) * (S_H / 2) + kwo + t];
            unsigned a2 = xw[g * (S_H / 2) + kwo + 4 + t];
            unsigned a3 = xw[(g + 8) * (S_H / 2) + kwo + 4 + t];

            // Packed weights (quad-uniform addresses -> one 32B sector each)
            const int r = kt * 2;
            unsigned w00 = (unsigned)__ldg(qbase + (size_t)r * NN + n0);
            unsigned w01 = (unsigned)__ldg(qbase + (size_t)(r + 1) * NN + n0);
            unsigned w10 = (unsigned)__ldg(qbase + (size_t)r * NN + n1);
            unsigned w11 = (unsigned)__ldg(qbase + (size_t)(r + 1) * NN + n1);

            unsigned b00 = dq(w00, sh, s20);
            unsigned b01 = dq(w01, sh, s20);
            unsigned b10 = dq(w10, sh, s21);
            unsigned b11 = dq(w11, sh, s21);

            mma16816(c0, a0, a1, a2, a3, b00, b01);
            mma16816(c1, a0, a1, a2, a3, b10, b11);
        }
    }

    // Lane(g,t) owns rows {g, g+8}, cols {2t, 2t+1} of each n8 tile.
    {
        float* p = g_partial + (size_t)kc * MM * NN;
        int col0 = nbase + 2 * t;
        int col1 = nbase + 8 + 2 * t;
        *reinterpret_cast<float2*>(p + (size_t)g * NN + col0)       = make_float2(c0[0], c0[1]);
        *reinterpret_cast<float2*>(p + (size_t)(g + 8) * NN + col0) = make_float2(c0[2], c0[3]);
        *reinterpret_cast<float2*>(p + (size_t)g * NN + col1)       = make_float2(c1[0], c1[1]);
        *reinterpret_cast<float2*>(p + (size_t)(g + 8) * NN + col1) = make_float2(c1[2], c1[3]);
    }
}

// One thread per 2 outputs: 65536 threads (27+ warps/SM), MLP 8 -> latency covered.
__global__ __launch_bounds__(256)
void reduce_bias_kernel(const float* __restrict__ bias, float* __restrict__ out) {
    const int i2 = blockIdx.x * 256 + threadIdx.x;     // 0..65535
    const float2* pp = reinterpret_cast<const float2*>(g_partial);

    float2 s = pp[i2];
#pragma unroll
    for (int c = 1; c < KCH; ++c) {
        float2 b = pp[(size_t)c * (MM * NN / 2) + i2];
        s.x += b.x; s.y += b.y;
    }

    const int idx = i2 * 2;
    const int n = idx & (NN - 1);
    float2 bv = *reinterpret_cast<const float2*>(bias + n);
    // Reference fp16 epilogue: fp16(dot) + fp16(bias) in fp16.
    __half h0 = __hadd(__float2half_rn(s.x), __float2half_rn(bv.x));
    __half h1 = __hadd(__float2half_rn(s.y), __float2half_rn(bv.y));
    float2 o;
    o.x = __half2float(h0);
    o.y = __half2float(h1);
    *reinterpret_cast<float2*>(out + idx) = o;
}

extern "C" void kernel_launch(void* const* d_in, const int* in_sizes, int n_in,
                              void* d_out, int out_size) {
    // Identify inputs by element count (all distinct).
    const float* x    = nullptr;   // 131072
    const int*   qw   = nullptr;   // 8388608
    const float* sc   = nullptr;   // 524288
    const float* bias = nullptr;   // 8192
    for (int i = 0; i < n_in; ++i) {
        switch (in_sizes[i]) {
            case 131072:  x    = (const float*)d_in[i]; break;
            case 8388608: qw   = (const int*)d_in[i];   break;
            case 524288:  sc   = (const float*)d_in[i]; break;
            case 8192:    bias = (const float*)d_in[i]; break;
            default: break;
        }
    }
    float* out = (float*)d_out;

    dim3 grid(NN / BLOCK_N, KCH);      // (64, 8)
    q4_gemm_mma<<<grid, 256>>>(x, qw, sc);

    reduce_bias_kernel<<<(MM * NN / 2) / 256, 256>>>(bias, out);
}

// round 7
// speedup vs baseline: 19.4626x; 1.2947x over previous
#include <cuda_runtime.h>
#include <cuda_fp16.h>
#include <cstdint>

#define MM 16
#define KK 8192
#define NN 8192
#define KCH 8            // split-K chunks
#define KC 1024          // k per chunk (8 groups of 128)
#define S_H 1032         // smem x row stride in halves (word stride 516 == 4 mod 32)

// fp32 partials: [KCH][M][N]
__device__ float g_partial[KCH * MM * NN];

__device__ __forceinline__ void mma16816(float c[4],
                                         unsigned a0, unsigned a1, unsigned a2, unsigned a3,
                                         unsigned b0, unsigned b1) {
    asm volatile(
        "mma.sync.aligned.m16n8k16.row.col.f32.f16.f16.f32 "
        "{%0,%1,%2,%3}, {%4,%5,%6,%7}, {%8,%9}, {%0,%1,%2,%3};\n"
        : "+f"(c[0]), "+f"(c[1]), "+f"(c[2]), "+f"(c[3])
        : "r"(a0), "r"(a1), "r"(a2), "r"(a3), "r"(b0), "r"(b1));
}

// Extract nibbles t and t+4 of word w (sh4 = 4*t) as exact fp16x2 (q-8, q'-8).
// Single shift then mask: no bit aliasing possible.
__device__ __forceinline__ unsigned dqx(unsigned w, unsigned sh4) {
    unsigned v = ((w >> sh4) & 0x000F000Fu) | 0x64006400u;   // (1024+q, 1024+q')
    __half2 hv = *reinterpret_cast<__half2*>(&v);
    __half2 r = __hsub2(hv, __float2half2_rn(1032.0f));      // exact q-8
    return *reinterpret_cast<unsigned*>(&r);
}

__global__ __launch_bounds__(128, 6)
void q4_gemm_mma(const float* __restrict__ x,
                 const int* __restrict__ qw,
                 const float* __restrict__ scales) {
    __shared__ __align__(16) __half xs[MM * S_H];

    const int tid = threadIdx.x;
    const int kc = blockIdx.y;
    const int warp = tid >> 5;
    const int lane = tid & 31;
    const int g = lane >> 2;        // 0..7
    const int t = lane & 3;         // 0..3
    const unsigned sh4 = 4u * t;
    const int nbase = blockIdx.x * 128 + warp * 32;

    // Stage x chunk [16][1024] -> fp16 smem with per-8-block half order [0,4,1,5,2,6,3,7].
    // Thread handles one 8-block per iter: 2 LDG.128 + 1 STS.128.
    for (int it = 0; it < 16; ++it) {
        int idx = it * 128 + tid;
        int m = idx >> 7;            // 0..15
        int b = idx & 127;           // 8-block index within chunk
        const float* xp = x + (size_t)m * KK + kc * KC + b * 8;
        float4 lo = *reinterpret_cast<const float4*>(xp);
        float4 hi = *reinterpret_cast<const float4*>(xp + 4);
        __half2 h0 = __floats2half2_rn(lo.x, hi.x);   // (k0, k4)
        __half2 h1 = __floats2half2_rn(lo.y, hi.y);   // (k1, k5)
        __half2 h2 = __floats2half2_rn(lo.z, hi.z);   // (k2, k6)
        __half2 h3 = __floats2half2_rn(lo.w, hi.w);   // (k3, k7)
        uint4 pk;
        pk.x = *reinterpret_cast<unsigned*>(&h0);
        pk.y = *reinterpret_cast<unsigned*>(&h1);
        pk.z = *reinterpret_cast<unsigned*>(&h2);
        pk.w = *reinterpret_cast<unsigned*>(&h3);
        *reinterpret_cast<uint4*>(&xs[m * S_H + b * 8]) = pk;
    }
    __syncthreads();

    // Accumulators: cm[j][r] for 4 interleaved n8-tiles (tile j = cols base+4c+j).
    float cm[4][4];
#pragma unroll
    for (int j = 0; j < 4; ++j)
#pragma unroll
        for (int r = 0; r < 4; ++r) cm[j][r] = 0.f;

    const unsigned* xw = reinterpret_cast<const unsigned*>(xs);
    const int arow0 = g * (S_H / 2);
    const int arow1 = (g + 8) * (S_H / 2);

    for (int grp = 0; grp < 8; ++grp) {
        const int gidx = kc * 8 + grp;
        // Scales for this lane's 8 C-columns (contiguous): cols nbase+8t .. +7
        const float4 sv0 = __ldg(reinterpret_cast<const float4*>(
            scales + (size_t)gidx * NN + nbase + 8 * t));
        const float4 sv1 = __ldg(reinterpret_cast<const float4*>(
            scales + (size_t)gidx * NN + nbase + 8 * t + 4));

        float ct[4][4];
#pragma unroll
        for (int j = 0; j < 4; ++j)
#pragma unroll
            for (int r = 0; r < 4; ++r) ct[j][r] = 0.f;

#pragma unroll
        for (int kk8 = 0; kk8 < 8; ++kk8) {
            const int kt = grp * 8 + kk8;          // k16 step within chunk
            // Weights: lane's uint4 = rows 2kt/2kt+1, cols nbase+4g..+3 (tiles 0..3)
            const int* rp = qw + (size_t)(kc * 128 + 2 * kt) * NN + nbase + 4 * g;
            uint4 w0 = __ldg(reinterpret_cast<const uint4*>(rp));        // b0 words
            uint4 w1 = __ldg(reinterpret_cast<const uint4*>(rp + NN));   // b1 words

            // A fragments (permuted layout; bank = (4g+t) mod 32 -> conflict-free)
            unsigned a0 = xw[arow0 + kt * 8 + t];
            unsigned a1 = xw[arow1 + kt * 8 + t];
            unsigned a2 = xw[arow0 + kt * 8 + 4 + t];
            unsigned a3 = xw[arow1 + kt * 8 + 4 + t];

            mma16816(ct[0], a0, a1, a2, a3, dqx(w0.x, sh4), dqx(w1.x, sh4));
            mma16816(ct[1], a0, a1, a2, a3, dqx(w0.y, sh4), dqx(w1.y, sh4));
            mma16816(ct[2], a0, a1, a2, a3, dqx(w0.z, sh4), dqx(w1.z, sh4));
            mma16816(ct[3], a0, a1, a2, a3, dqx(w0.w, sh4), dqx(w1.w, sh4));
        }

        // Apply group scale: C lane cols are (2t -> s_lo[j]), (2t+1 -> s_hi[j])
        const float slo[4] = {sv0.x, sv0.y, sv0.z, sv0.w};
        const float shi[4] = {sv1.x, sv1.y, sv1.z, sv1.w};
#pragma unroll
        for (int j = 0; j < 4; ++j) {
            cm[j][0] += ct[j][0] * slo[j];
            cm[j][1] += ct[j][1] * shi[j];
            cm[j][2] += ct[j][2] * slo[j];
            cm[j][3] += ct[j][3] * shi[j];
        }
    }

    // Store partials. Tile j mma-col c -> global col nbase + 4c + j, so the j-vectors
    // are contiguous float4s: rows {g, g+8}, cols {nbase+8t(+4)}.
    {
        float* p = g_partial + (size_t)kc * MM * NN;
        const int col = nbase + 8 * t;
        float4 v00 = make_float4(cm[0][0], cm[1][0], cm[2][0], cm[3][0]);
        float4 v01 = make_float4(cm[0][1], cm[1][1], cm[2][1], cm[3][1]);
        float4 v10 = make_float4(cm[0][2], cm[1][2], cm[2][2], cm[3][2]);
        float4 v11 = make_float4(cm[0][3], cm[1][3], cm[2][3], cm[3][3]);
        *reinterpret_cast<float4*>(p + (size_t)g * NN + col)           = v00;
        *reinterpret_cast<float4*>(p + (size_t)g * NN + col + 4)       = v01;
        *reinterpret_cast<float4*>(p + (size_t)(g + 8) * NN + col)     = v10;
        *reinterpret_cast<float4*>(p + (size_t)(g + 8) * NN + col + 4) = v11;
    }
}

__global__ __launch_bounds__(128)
void reduce_bias_kernel(const float* __restrict__ bias, float* __restrict__ out) {
    const int i2 = blockIdx.x * 128 + threadIdx.x;     // one thread per 2 outputs
    const float2* pp = reinterpret_cast<const float2*>(g_partial);

    float2 s = pp[i2];
#pragma unroll
    for (int c = 1; c < KCH; ++c) {
        float2 b = pp[(size_t)c * (MM * NN / 2) + i2];
        s.x += b.x; s.y += b.y;
    }

    const int idx = i2 * 2;
    const int n = idx & (NN - 1);
    float2 bv = *reinterpret_cast<const float2*>(bias + n);
    // Reference fp16 epilogue: fp16(dot) + fp16(bias) in fp16.
    __half h0 = __hadd(__float2half_rn(s.x), __float2half_rn(bv.x));
    __half h1 = __hadd(__float2half_rn(s.y), __float2half_rn(bv.y));
    float2 o;
    o.x = __half2float(h0);
    o.y = __half2float(h1);
    *reinterpret_cast<float2*>(out + idx) = o;
}

extern "C" void kernel_launch(void* const* d_in, const int* in_sizes, int n_in,
                              void* d_out, int out_size) {
    // Identify inputs by element count (all distinct).
    const float* x    = nullptr;   // 131072
    const int*   qw   = nullptr;   // 8388608
    const float* sc   = nullptr;   // 524288
    const float* bias = nullptr;   // 8192
    for (int i = 0; i < n_in; ++i) {
        switch (in_sizes[i]) {
            case 131072:  x    = (const float*)d_in[i]; break;
            case 8388608: qw   = (const int*)d_in[i];   break;
            case 524288:  sc   = (const float*)d_in[i]; break;
            case 8192:    bias = (const float*)d_in[i]; break;
            default: break;
        }
    }
    float* out = (float*)d_out;

    dim3 grid(NN / 128, KCH);          // (64, 8), 128 threads (4 warps, n32 each)
    q4_gemm_mma<<<grid, 128>>>(x, qw, sc);

    reduce_bias_kernel<<<(MM * NN / 2) / 128, 128>>>(bias, out);
}